// round 15
// baseline (speedup 1.0000x reference)
#include <cuda_runtime.h>
#include <cuda_fp16.h>
#include <math.h>
#include <stdint.h>

// ===========================================================================
// mma.sync m16n8k16 row.col fp16*fp16 -> f32 + ldmatrix + cp.async helpers
// ===========================================================================
__device__ __forceinline__ void mma_f16(float* c, const uint32_t* a, const uint32_t* b)
{
    asm volatile(
        "mma.sync.aligned.m16n8k16.row.col.f32.f16.f16.f32 "
        "{%0,%1,%2,%3}, {%4,%5,%6,%7}, {%8,%9}, {%0,%1,%2,%3};"
        : "+f"(c[0]), "+f"(c[1]), "+f"(c[2]), "+f"(c[3])
        : "r"(a[0]), "r"(a[1]), "r"(a[2]), "r"(a[3]), "r"(b[0]), "r"(b[1]));
}
__device__ __forceinline__ void ldsm_x4(uint32_t* r, uint32_t addr)
{
    asm volatile(
        "ldmatrix.sync.aligned.m8n8.x4.shared.b16 {%0,%1,%2,%3}, [%4];"
        : "=r"(r[0]), "=r"(r[1]), "=r"(r[2]), "=r"(r[3]) : "r"(addr));
}
__device__ __forceinline__ void cp16(uint32_t dst, const void* src)
{
    asm volatile("cp.async.cg.shared.global [%0], [%1], 16;" :: "r"(dst), "l"(src));
}
// 4B cp.async with zero-fill when sz==0 (src-size operand)
__device__ __forceinline__ void cp4z(uint32_t dst, const void* src, uint32_t sz)
{
    asm volatile("cp.async.ca.shared.global [%0], [%1], 4, %2;"
                 :: "r"(dst), "l"(src), "r"(sz));
}
#define CP_COMMIT asm volatile("cp.async.commit_group;" ::: "memory")
#define CP_WAIT1  asm volatile("cp.async.wait_group 1;" ::: "memory")
#define CP_WAIT0  asm volatile("cp.async.wait_group 0;" ::: "memory")

__device__ __forceinline__ uint32_t packhalf2(float c0, float c1)
{
    return ((uint32_t)__half_as_ushort(__float2half_rn(c1)) << 16)
         | __half_as_ushort(__float2half_rn(c0));
}
__device__ __forceinline__ float2 unpackhalf2(uint32_t v)
{
    __half2 h = *(__half2*)&v;
    return __half22float2(h);
}

// ===========================================================================
// Scratch buffers (activations in fp16 hi-pair format [b][ch/2][px])
// ===========================================================================
__device__ uint32_t g_w8_hp [(size_t)4*256*128*128];
__device__ uint32_t g_bwt_hp[(size_t)4*256*128*128];
__device__ uint32_t g_x_hp  [(size_t)4*32*256*256];
__device__ uint32_t g_r1_hp [(size_t)4*32*128*128];
__device__ uint32_t g_r2_hp [(size_t)4*256*128*128];
__device__ uint32_t g_wv_hp [(size_t)4*32*256*256];
__device__ float    g_pool  [(size_t)4*2*128*128];
__device__ float    g_sal   [(size_t)4*128*128];
__device__ float    g_m     [4*512];
__device__ float    g_cal   [4*512];
// weight images: exact smem layout, [coT][cc16][tap*512 + co*8 + swz(pos)]
__device__ uint32_t g_wi1[32*9*512];
__device__ uint32_t g_wi2[8*4*9*512];
__device__ uint32_t g_wi3[4*9*512];
__device__ uint32_t g_wif[4*512];
__device__ uint32_t g_wic[(size_t)4*8*32*512];

// ===========================================================================
// Weight prep: f32 [CO][CI][KS2] -> swizzled smem-image u32 (fp16 ci-pairs)
// ===========================================================================
__device__ __forceinline__ void packone(const float* __restrict__ w,
                                        uint32_t* __restrict__ wp,
                                        int CO, int CI, int KS2, int i)
{
    int chunkU = KS2*512;
    int perCoT = (CI/16)*chunkU;
    int coT = i / perCoT;
    int rem = i - coT*perCoT;
    int cc  = rem / chunkU;
    int u   = rem - cc*chunkU;
    int tap = u >> 9;
    int r   = u & 511;
    int co  = r >> 3, pos = r & 7;
    int xb  = (co>>2)&1;
    int cip = ((((pos>>2)^xb)<<2) | (pos&3));
    int ci  = cc*16 + 2*cip;
    int cog = coT*64 + co;
    wp[i] = packhalf2(w[((size_t)cog*CI + ci)*KS2 + tap],
                      w[((size_t)cog*CI + ci+1)*KS2 + tap]);
}
__global__ void packall_img(const float* __restrict__ w1, const float* __restrict__ w2,
                            const float* __restrict__ w3, const float* __restrict__ wf,
                            uint32_t* __restrict__ o1, uint32_t* __restrict__ o2,
                            uint32_t* __restrict__ o3, uint32_t* __restrict__ of)
{
    int i = blockIdx.x*256 + threadIdx.x;
    if (i < 147456)            packone(w1, o1, 64, 512, 9, i);
    else if (i < 294912)       packone(w2, o2, 512, 64, 9, i - 147456);
    else if (i < 313344)       packone(w3, o3, 64, 64, 9, i - 294912);
    else if (i < 315392)       packone(wf, of, 64, 64, 1, i - 313344);
}
__global__ void packwcal_img(const float* __restrict__ w, const float* __restrict__ cal,
                             uint32_t* __restrict__ wp)
{
    int i = blockIdx.x*256 + threadIdx.x;   // 4*131072
    int b = i >> 17;
    int rem = i & 131071;
    int coT = rem >> 14;
    int rem2 = rem & 16383;
    int cc  = rem2 >> 9;
    int u   = rem2 & 511;
    int co  = u >> 3, pos = u & 7;
    int xb  = (co>>2)&1;
    int cip = ((((pos>>2)^xb)<<2) | (pos&3));
    int ci  = cc*16 + 2*cip;
    int cog = coT*64 + co;
    wp[i] = packhalf2(w[cog*512 + ci]   * cal[b*512 + ci],
                      w[cog*512 + ci+1] * cal[b*512 + ci+1]);
}

// ===========================================================================
// K1: BWT  x -> bwt hi-pair, plus x repacked to hi-pair (for residual)
// ===========================================================================
__global__ void bwt_kernel(const float* __restrict__ x,
                           uint32_t* __restrict__ ohp, uint32_t* __restrict__ xhp)
{
    int idx = blockIdx.x * 256 + threadIdx.x;   // 4*32*128*128
    int j  = idx & 127;
    int i  = (idx >> 7) & 127;
    int cp = (idx >> 14) & 31;
    int b  = idx >> 19;
    const float* xp0 = x + ((size_t)(b*64 + 2*cp)*256 + 2*i)*256 + 2*j;
    const float* xp1 = xp0 + 65536;
    float2 r0 = *(const float2*)xp0, r1 = *(const float2*)(xp0 + 256);
    float2 s0 = *(const float2*)xp1, s1 = *(const float2*)(xp1 + 256);
    size_t xb = ((size_t)(b*32 + cp) << 16) + (size_t)(2*i)*256 + 2*j;
    xhp[xb      ] = packhalf2(r0.x, s0.x);
    xhp[xb + 1  ] = packhalf2(r0.y, s0.y);
    xhp[xb + 256] = packhalf2(r1.x, s1.x);
    xhp[xb + 257] = packhalf2(r1.y, s1.y);
    float a1 = r0.x*0.5f, a3 = r0.y*0.5f, a2 = r1.x*0.5f, a4 = r1.y*0.5f;
    float b1 = s0.x*0.5f, b3 = s0.y*0.5f, b2 = s1.x*0.5f, b4 = s1.y*0.5f;
    int p = (i << 7) + j;
    size_t obP = ((size_t)(b*256 + cp) << 14) + p;
    const size_t gsP = (size_t)32 << 14;
#define BWT_EMIT(k, s1_, s2_, s3_, s4_) \
    ohp[obP + k*gsP] = packhalf2(s1_ a1 s2_ a2 s3_ a3 s4_ a4, \
                                 s1_ b1 s2_ b2 s3_ b3 s4_ b4);
    BWT_EMIT(0, +, +, +, +)
    BWT_EMIT(1, -, -, +, +)
    BWT_EMIT(2, -, +, -, +)
    BWT_EMIT(3, +, -, -, +)
    BWT_EMIT(4, +, +, -, -)
    BWT_EMIT(5, -, +, +, -)
    BWT_EMIT(6, +, -, +, -)
    BWT_EMIT(7, -, -, -, -)
#undef BWT_EMIT
}

// ===========================================================================
// Implicit-GEMM conv, single-term fp16 mma.sync.
// m64 warp tile: CTA = 32 rows x 16 cols pixels, warp covers 4 pixel rows.
// A staged via 4B cp.async (zero-fill OOB) directly into swizzled smem,
// 3-stage A + 3-stage W, ONE sync per chunk.
// ===========================================================================
template<int CIN, int COUT, int H, int KS, int KCH,
         bool RELU, bool ADD_OUT, bool ADD_HP, bool SAL, bool WPERB,
         bool OUTF32, bool OUTPK, int CIN2>
__global__ __launch_bounds__(256, 1)
void mmaconv_kernel(const uint32_t* __restrict__ in_hp,
                    const uint32_t* __restrict__ wimg,
                    const float* __restrict__ sal,
                    const uint32_t* __restrict__ addhp,
                    const uint32_t* __restrict__ in2_hp,
                    const uint32_t* __restrict__ wimg2,
                    float* outf, uint32_t* __restrict__ outhp)
{
    constexpr int KS2  = KS*KS;
    constexpr int PAD  = KS/2;
    constexpr int HCX  = 16 + KS - 1;
    constexpr int HCY  = 32 + KS - 1;
    constexpr int HEL  = HCX*HCY;
    constexpr int NSUB = KCH/16;
    constexpr int APL  = HEL*32;            // bytes per 16-ci sub-plane
    constexpr int ASTG = NSUB*APL;          // bytes per A stage
    constexpr int WCH  = NSUB*KS2*2048;     // bytes per W chunk
    constexpr int NC   = CIN/KCH;
    constexpr int ACNT = (KCH/2)*HEL;       // u32 per A stage
    constexpr int NG   = NSUB*KS2*128;      // 16B granules per W chunk
    constexpr int HW   = H*H;

    extern __shared__ __align__(16) char smem[];
    const uint32_t smemBase = (uint32_t)__cvta_generic_to_shared(smem);
    const uint32_t wSmem    = smemBase + 3*ASTG;

    const int t    = threadIdx.x;
    const int lane = t & 31, wid = t >> 5;
    const int g    = lane >> 2;
    const int c0   = (lane & 3) * 2;
    const int bx0  = blockIdx.x * 16;
    const int by0  = blockIdx.y * 32;
    const int z    = blockIdx.z;
    const int coT  = z % (COUT/64);
    const int b    = z / (COUT/64);

    const int ltile = lane >> 3, lrow = lane & 7;
    const int lt_lo = ltile & 1;
    const int lt_h  = ltile >> 1;

    uint32_t boff[4];
    #pragma unroll
    for (int nfp = 0; nfp < 4; ++nfp) {
        int cr = nfp*16 + lt_lo*8 + lrow;
        boff[nfp] = (uint32_t)(cr*32 + ((lt_h ^ ((cr>>2)&1)) << 4));
    }

    const size_t bciHW = (size_t)(b*(CIN/2))*HW;
    constexpr int NC16 = CIN/16;
    const uint32_t* wChunk0 = wimg
        + (WPERB ? (size_t)b*(COUT/64)*NC16*KS2*512 : 0)
        + (size_t)coT*NC16*KS2*512;

    float acc[4][8][4];
    #pragma unroll
    for (int mf = 0; mf < 4; ++mf)
        #pragma unroll
        for (int nf = 0; nf < 8; ++nf)
            #pragma unroll
            for (int q = 0; q < 4; ++q) acc[mf][nf][q] = 0.f;

    // A staging: 4B cp.async straight into swizzled slots, zero-fill OOB
    auto issueA = [&](const uint32_t* src, size_t bbase, int chcnt2, int cc, int st) {
        const uint32_t dstB = smemBase + st*ASTG;
        for (int k = t; k < (chcnt2)*HEL; k += 256) {
            int cip = k / HEL;
            int pix = k - cip*HEL;
            int py  = pix / HCX, px = pix - py*HCX;
            int gy  = by0 + py - PAD, gx = bx0 + px - PAD;
            bool ok = (gy >= 0 && gy < H && gx >= 0 && gx < H);
            int gyc = ok ? gy : 0, gxc = ok ? gx : 0;
            int sub = cip >> 3, c8 = cip & 7;
            int u = sub*(HEL*8) + pix*8
                  + ((((c8>>2) ^ ((pix>>2)&1)) << 2) | (c8 & 3));
            cp4z(dstB + u*4,
                 src + bbase + (size_t)(cc*chcnt2 + cip)*HW + gyc*H + gxc,
                 ok ? 4u : 0u);
        }
    };
    auto cpW = [&](int cc, int st) {
        const uint32_t* src = wChunk0 + (size_t)cc*NSUB*KS2*512;
        uint32_t dst = wSmem + st*WCH;
        #pragma unroll
        for (int k = t; k < NG; k += 256)
            cp16(dst + k*16, src + k*4);
    };
    auto computeTap = [&](uint32_t aHi, uint32_t wTap, int dy, int dx) {
        uint32_t bh[8][2];
        #pragma unroll
        for (int nfp = 0; nfp < 4; ++nfp) {
            uint32_t tmp[4];
            ldsm_x4(tmp, wTap + boff[nfp]);
            bh[2*nfp][0] = tmp[0]; bh[2*nfp+1][0] = tmp[1];
            bh[2*nfp][1] = tmp[2]; bh[2*nfp+1][1] = tmp[3];
        }
        #pragma unroll
        for (int mf = 0; mf < 4; ++mf) {
            const int pyb = (wid << 2) + mf + dy;
            const int pix = pyb*HCX + dx + lt_lo*8 + lrow;
            uint32_t aoff = (uint32_t)(pix*32 + ((lt_h ^ ((pix>>2)&1)) << 4));
            uint32_t ah[4];
            ldsm_x4(ah, aHi + aoff);
            #pragma unroll
            for (int nf = 0; nf < 8; ++nf)
                mma_f16(acc[mf][nf], ah, bh[nf]);
        }
    };
    auto compute = [&](int st) {
        #pragma unroll
        for (int s = 0; s < NSUB; ++s) {
            const uint32_t aHi = smemBase + st*ASTG + s*APL;
            const uint32_t wB  = wSmem + st*WCH + s*KS2*2048;
            #pragma unroll
            for (int tap = 0; tap < KS2; ++tap)
                computeTap(aHi, wB + (uint32_t)(tap*2048), tap/KS, tap - (tap/KS)*KS);
        }
    };

    // ---- pipelined chunk loop: ONE sync per chunk, 3-stage A and W ----
    issueA(in_hp, bciHW, KCH/2, 0, 0); cpW(0, 0); CP_COMMIT;
    if (NC > 1) { issueA(in_hp, bciHW, KCH/2, 1, 1); cpW(1, 1); }
    CP_COMMIT;
    CP_WAIT1;
    __syncthreads();
    #pragma unroll 1
    for (int cc = 0; cc < NC; ++cc) {
        compute(cc % 3);
        if (cc + 1 < NC) {
            if (cc + 2 < NC) {
                issueA(in_hp, bciHW, KCH/2, cc + 2, (cc + 2) % 3);
                cpW(cc + 2, (cc + 2) % 3);
            }
            CP_COMMIT;
            CP_WAIT1;
            __syncthreads();
        }
    }

    // ---- fused phase 2: relu + 1x1 conv of in2 accumulated on top ----
    if constexpr (CIN2 > 0) {
        #pragma unroll
        for (int mf = 0; mf < 4; ++mf)
            #pragma unroll
            for (int nf = 0; nf < 8; ++nf)
                #pragma unroll
                for (int q = 0; q < 4; ++q)
                    acc[mf][nf][q] = fmaxf(acc[mf][nf][q], 0.f);
        const size_t bci2 = (size_t)(b*(CIN2/2))*HW;
        #pragma unroll 1
        for (int cc = 0; cc < CIN2/16; ++cc) {
            __syncthreads();                       // release stage 0
            issueA(in2_hp, bci2, 8, cc, 0);        // 16 ci -> 8 pair planes
            for (int k = t; k < 512; k += 256)
                ((uint32_t*)(smem + 3*ASTG))[k] = wimg2[cc*512 + k];
            CP_COMMIT;
            CP_WAIT0;
            __syncthreads();
            computeTap(smemBase, wSmem, PAD, PAD);
        }
    }

    // ---- epilogue ----
    #pragma unroll
    for (int mf = 0; mf < 4; ++mf) {
        const int gy  = by0 + (wid << 2) + mf;
        const int gx0 = bx0 + g;
        const int gx8 = gx0 + 8;
        float s0 = 1.f, s8 = 1.f;
        if (SAL) {
            s0 = sal[((size_t)b*H + gy)*H + gx0];
            s8 = sal[((size_t)b*H + gy)*H + gx8];
        }
        #pragma unroll
        for (int nf = 0; nf < 8; ++nf) {
            const int co = coT*64 + nf*8 + c0;
            size_t o0 = ((size_t)(b*COUT + co)*H + gy)*H + gx0;
            size_t o1 = o0 + (size_t)H*H;
            size_t o2 = ((size_t)(b*COUT + co)*H + gy)*H + gx8;
            size_t o3 = o2 + (size_t)H*H;
            float v0 = acc[mf][nf][0]*s0, v1 = acc[mf][nf][1]*s0;
            float v2 = acc[mf][nf][2]*s8, v3 = acc[mf][nf][3]*s8;
            if (RELU && CIN2 == 0) {
                v0 = fmaxf(v0, 0.f); v1 = fmaxf(v1, 0.f);
                v2 = fmaxf(v2, 0.f); v3 = fmaxf(v3, 0.f);
            }
            if (ADD_OUT) { v0 += outf[o0]; v1 += outf[o1]; v2 += outf[o2]; v3 += outf[o3]; }
            size_t pb = ((size_t)(b*(COUT/2) + (co >> 1)))*HW + (size_t)gy*H;
            if (ADD_HP) {
                float2 h0 = unpackhalf2(addhp[pb + gx0]);
                float2 h8 = unpackhalf2(addhp[pb + gx8]);
                v0 += h0.x; v1 += h0.y; v2 += h8.x; v3 += h8.y;
            }
            if (OUTF32) { outf[o0] = v0; outf[o1] = v1; outf[o2] = v2; outf[o3] = v3; }
            if (OUTPK) {
                outhp[pb + gx0] = packhalf2(v0, v1);
                outhp[pb + gx8] = packhalf2(v2, v3);
            }
        }
    }
}

// ===========================================================================
// Attention glue kernels (hp inputs)
// ===========================================================================
__global__ void chanpool_kernel(const uint32_t* __restrict__ r2hp, float* __restrict__ pool)
{
    int p = blockIdx.x * 256 + threadIdx.x;
    int b = blockIdx.y;
    const uint32_t* base = r2hp + (((size_t)b*256) << 14) + p;
    float mx = -3.4e38f, s = 0.f;
    #pragma unroll 8
    for (int c = 0; c < 256; ++c) {
        float2 f = unpackhalf2(base[(size_t)c << 14]);
        mx = fmaxf(mx, fmaxf(f.x, f.y));
        s += f.x + f.y;
    }
    pool[(((size_t)(b*2    )) << 14) + p] = mx;
    pool[(((size_t)(b*2 + 1)) << 14) + p] = s * (1.f/512.f);
}

__global__ void salconv_kernel(const float* __restrict__ pool,
                               const float* __restrict__ wsal,
                               float* __restrict__ sal)
{
    int p = blockIdx.x * 256 + threadIdx.x;
    int b = blockIdx.y;
    int y = p >> 7, x = p & 127;
    float a = 0.f;
    #pragma unroll
    for (int c = 0; c < 2; ++c) {
        const float* pp = pool + (((size_t)(b*2 + c)) << 14);
        #pragma unroll
        for (int ky = 0; ky < 5; ++ky) {
            int iy = y + ky - 2;
            if (iy < 0 || iy >= 128) continue;
            #pragma unroll
            for (int kx = 0; kx < 5; ++kx) {
                int ix = x + kx - 2;
                if (ix < 0 || ix >= 128) continue;
                a += wsal[c*25 + ky*5 + kx] * pp[(iy << 7) + ix];
            }
        }
    }
    sal[(((size_t)b) << 14) + p] = 1.f / (1.f + expf(-a));
}

__global__ void wmean_kernel(const uint32_t* __restrict__ r2hp,
                             const float* __restrict__ sal,
                             float* __restrict__ m)
{
    int cp = blockIdx.x, b = blockIdx.y;
    const uint32_t* r = r2hp + (((size_t)(b*256 + cp)) << 14);
    const float* s = sal + (((size_t)b) << 14);
    float s0 = 0.f, s1 = 0.f;
    for (int i = threadIdx.x; i < 4096; i += 256) {
        uint4 rv = *(const uint4*)(r + i*4);
        float4 sv = *(const float4*)(s + i*4);
        float2 f0 = unpackhalf2(rv.x), f1 = unpackhalf2(rv.y);
        float2 f2 = unpackhalf2(rv.z), f3 = unpackhalf2(rv.w);
        s0 += f0.x*sv.x + f1.x*sv.y + f2.x*sv.z + f3.x*sv.w;
        s1 += f0.y*sv.x + f1.y*sv.y + f2.y*sv.z + f3.y*sv.w;
    }
    #pragma unroll
    for (int o = 16; o > 0; o >>= 1) {
        s0 += __shfl_xor_sync(0xffffffffu, s0, o);
        s1 += __shfl_xor_sync(0xffffffffu, s1, o);
    }
    __shared__ float red[8][2];
    if ((threadIdx.x & 31) == 0) {
        red[threadIdx.x >> 5][0] = s0;
        red[threadIdx.x >> 5][1] = s1;
    }
    __syncthreads();
    if (threadIdx.x == 0) {
        float t0 = 0.f, t1 = 0.f;
        #pragma unroll
        for (int i = 0; i < 8; ++i) { t0 += red[i][0]; t1 += red[i][1]; }
        m[b*512 + 2*cp    ] = t0 * (1.f/16384.f);
        m[b*512 + 2*cp + 1] = t1 * (1.f/16384.f);
    }
}

__global__ void calmlp_kernel(const float* __restrict__ m,
                              const float* __restrict__ wca1,
                              const float* __restrict__ wca2,
                              float* __restrict__ cal)
{
    int b = blockIdx.x;
    __shared__ float sm[512];
    __shared__ float sy1[32];
    for (int i = threadIdx.x; i < 512; i += 256) sm[i] = m[b*512 + i];
    __syncthreads();
    if (threadIdx.x < 32) {
        float a = 0.f;
        for (int c = 0; c < 512; ++c) a += wca1[threadIdx.x*512 + c] * sm[c];
        sy1[threadIdx.x] = fmaxf(a, 0.f);
    }
    __syncthreads();
    for (int c = threadIdx.x; c < 512; c += 256) {
        float a = 0.f;
        #pragma unroll
        for (int j = 0; j < 32; ++j) a += wca2[c*32 + j] * sy1[j];
        cal[b*512 + c] = 1.f / (1.f + expf(-a));
    }
}

// ===========================================================================
// K9: IBWT (hp in from conv8) -> hi-pair packed output
// ===========================================================================
__global__ void ibwt_kernel(const uint32_t* __restrict__ rhp, uint32_t* __restrict__ ohp)
{
    int idx = blockIdx.x * 256 + threadIdx.x;
    int j  = idx & 127;
    int i  = (idx >> 7) & 127;
    int cp = (idx >> 14) & 31;
    int b  = idx >> 19;
    int p  = (i << 7) + j;
    size_t base = ((size_t)(b*256 + cp) << 14) + p;
    const size_t gsP = (size_t)32 << 14;
    float pe[8], qe[8];
    #pragma unroll
    for (int s = 0; s < 8; ++s) {
        float2 f = unpackhalf2(rhp[base + s*gsP]);
        pe[s] = f.x*0.5f; qe[s] = f.y*0.5f;
    }
    float a00p = pe[0]-pe[1]-pe[2]+pe[3]+pe[4]-pe[5]+pe[6]-pe[7];
    float a10p = pe[0]-pe[1]+pe[2]-pe[3]-pe[4]+pe[5]-pe[6]+pe[7];
    float a01p = pe[0]+pe[1]-pe[2]-pe[3]-pe[4]-pe[5]+pe[6]+pe[7];
    float a11p = pe[0]+pe[1]+pe[2]+pe[3]+pe[4]+pe[5]+pe[6]+pe[7];
    float a00q = qe[0]-qe[1]-qe[2]+qe[3]+qe[4]-qe[5]+qe[6]-qe[7];
    float a10q = qe[0]-qe[1]+qe[2]-qe[3]-qe[4]+qe[5]-qe[6]+qe[7];
    float a01q = qe[0]+qe[1]-qe[2]-qe[3]-qe[4]-qe[5]+qe[6]+qe[7];
    float a11q = qe[0]+qe[1]+qe[2]+qe[3]+qe[4]+qe[5]+qe[6]+qe[7];
    size_t off = ((size_t)(b*32 + cp) << 16) + ((size_t)(2*i))*256 + 2*j;
    ohp[off      ] = packhalf2(a00p, a00q);
    ohp[off + 1  ] = packhalf2(a01p, a01q);
    ohp[off + 256] = packhalf2(a10p, a10q);
    ohp[off + 257] = packhalf2(a11p, a11q);
}

// ===========================================================================
// Launch
// ===========================================================================
extern "C" void kernel_launch(void* const* d_in, const int* in_sizes, int n_in,
                              void* d_out, int out_size)
{
    const float* x       = (const float*)d_in[0];
    const float* w_body1 = (const float*)d_in[1];
    const float* w_body2 = (const float*)d_in[2];
    const float* w_sal   = (const float*)d_in[3];
    const float* w_ca1   = (const float*)d_in[4];
    const float* w_ca2   = (const float*)d_in[5];
    const float* w_1x1   = (const float*)d_in[6];
    const float* w_3x3   = (const float*)d_in[7];
    const float* w_final = (const float*)d_in[8];
    float* out = (float*)d_out;

    float *pool, *sal, *m, *cal;
    uint32_t *w8_hp, *bwt_hp, *x_hp, *r1_hp, *r2_hp, *wv_hp;
    uint32_t *wi1, *wi2, *wi3, *wif, *wic;
    cudaGetSymbolAddress((void**)&w8_hp,  g_w8_hp);
    cudaGetSymbolAddress((void**)&bwt_hp, g_bwt_hp);
    cudaGetSymbolAddress((void**)&x_hp,   g_x_hp);
    cudaGetSymbolAddress((void**)&r1_hp,  g_r1_hp);
    cudaGetSymbolAddress((void**)&r2_hp,  g_r2_hp);
    cudaGetSymbolAddress((void**)&wv_hp,  g_wv_hp);
    cudaGetSymbolAddress((void**)&pool,   g_pool);
    cudaGetSymbolAddress((void**)&sal,    g_sal);
    cudaGetSymbolAddress((void**)&m,      g_m);
    cudaGetSymbolAddress((void**)&cal,    g_cal);
    cudaGetSymbolAddress((void**)&wi1,    g_wi1);
    cudaGetSymbolAddress((void**)&wi2,    g_wi2);
    cudaGetSymbolAddress((void**)&wi3,    g_wi3);
    cudaGetSymbolAddress((void**)&wif,    g_wif);
    cudaGetSymbolAddress((void**)&wic,    g_wic);

    // smem: KS=3 MF=4 -> 3*(34*18*32) + 3*(9*2048) = 58752 + 55296 = 114048
    //       KS=1 KCH=32 -> 3*(2*32*16*32) + 3*(2*2048) = 98304 + 12288 = 110592
    constexpr int SM3    = 3*(34*18*32) + 3*(9*2048);
    constexpr int SM1K32 = 3*(2*32*16*32) + 3*(2*2048);
    cudaFuncSetAttribute(
        (const void*)mmaconv_kernel<512,64,128,3,16, true,false,false,false,false,false,true,0>,
        cudaFuncAttributeMaxDynamicSharedMemorySize, SM3);
    cudaFuncSetAttribute(
        (const void*)mmaconv_kernel<64,512,128,3,16, false,false,false,false,false,false,true,0>,
        cudaFuncAttributeMaxDynamicSharedMemorySize, SM3);
    cudaFuncSetAttribute(
        (const void*)mmaconv_kernel<512,512,128,1,32, false,false,true,true,true,false,true,0>,
        cudaFuncAttributeMaxDynamicSharedMemorySize, SM1K32);
    cudaFuncSetAttribute(
        (const void*)mmaconv_kernel<64,64,256,3,16, true,false,false,false,false,true,false,64>,
        cudaFuncAttributeMaxDynamicSharedMemorySize, SM3);

    // 0) all static weight images in one launch
    packall_img<<<(315392 + 255)/256, 256>>>(w_body1, w_body2, w_3x3, w_final,
                                             wi1, wi2, wi3, wif);

    // 1) BWT (hi-pair) + x repack
    bwt_kernel<<<8192, 256>>>(x, bwt_hp, x_hp);
    // 2) body1 3x3 (512 -> 64) + relu -> r1 hi-pair
    mmaconv_kernel<512,64,128,3,16, true,false,false,false,false,false,true,0>
        <<<dim3(8,4,4), 256, SM3>>>(bwt_hp, wi1, nullptr, nullptr, nullptr, nullptr,
                                    nullptr, r1_hp);
    // 3) body2 3x3 (64 -> 512) -> r2 hi-pair
    mmaconv_kernel<64,512,128,3,16, false,false,false,false,false,false,true,0>
        <<<dim3(8,4,32), 256, SM3>>>(r1_hp, wi2, nullptr, nullptr, nullptr, nullptr,
                                     nullptr, r2_hp);
    // 4) channel pooling (hp)
    chanpool_kernel<<<dim3(64,4), 256>>>(r2_hp, pool);
    // 5) 5x5 conv + sigmoid -> sal
    salconv_kernel<<<dim3(64,4), 256>>>(pool, w_sal, sal);
    // 6) weighted channel means (hp, pairs)
    wmean_kernel<<<dim3(256,4), 256>>>(r2_hp, sal, m);
    // 7) channel attention MLP
    calmlp_kernel<<<4, 256>>>(m, w_ca1, w_ca2, cal);
    // 7b) 1x1 weights with cal folded (per batch), swizzled image
    packwcal_img<<<(4*8*32*512)/256, 256>>>(w_1x1, cal, wic);
    // 8) 1x1 conv (512->512), KCH=32: sal epilogue, += x_bwt hp -> w8 hp
    mmaconv_kernel<512,512,128,1,32, false,false,true,true,true,false,true,0>
        <<<dim3(8,4,32), 256, SM1K32>>>(r2_hp, wic, sal, bwt_hp, nullptr, nullptr,
                                        nullptr, w8_hp);
    // 9) IBWT (hp in) -> hi-pair wave
    ibwt_kernel<<<8192, 256>>>(w8_hp, wv_hp);
    // 10+11 fused) out = relu(conv3x3(wave)) + conv1x1(x)
    mmaconv_kernel<64,64,256,3,16, true,false,false,false,false,true,false,64>
        <<<dim3(16,8,4), 256, SM3>>>(wv_hp, wi3, nullptr, nullptr, x_hp, wif,
                                     out, nullptr);
}

// round 17
// speedup vs baseline: 1.0522x; 1.0522x over previous
#include <cuda_runtime.h>
#include <cuda_fp16.h>
#include <math.h>
#include <stdint.h>

// ===========================================================================
// mma.sync m16n8k16 row.col fp16*fp16 -> f32 + ldmatrix + cp.async helpers
// ===========================================================================
__device__ __forceinline__ void mma_f16(float* c, const uint32_t* a, const uint32_t* b)
{
    asm volatile(
        "mma.sync.aligned.m16n8k16.row.col.f32.f16.f16.f32 "
        "{%0,%1,%2,%3}, {%4,%5,%6,%7}, {%8,%9}, {%0,%1,%2,%3};"
        : "+f"(c[0]), "+f"(c[1]), "+f"(c[2]), "+f"(c[3])
        : "r"(a[0]), "r"(a[1]), "r"(a[2]), "r"(a[3]), "r"(b[0]), "r"(b[1]));
}
__device__ __forceinline__ void ldsm_x4(uint32_t* r, uint32_t addr)
{
    asm volatile(
        "ldmatrix.sync.aligned.m8n8.x4.shared.b16 {%0,%1,%2,%3}, [%4];"
        : "=r"(r[0]), "=r"(r[1]), "=r"(r[2]), "=r"(r[3]) : "r"(addr));
}
__device__ __forceinline__ void cp16(uint32_t dst, const void* src)
{
    asm volatile("cp.async.cg.shared.global [%0], [%1], 16;" :: "r"(dst), "l"(src));
}
__device__ __forceinline__ void cp4(uint32_t dst, const void* src)
{
    asm volatile("cp.async.ca.shared.global [%0], [%1], 4;" :: "r"(dst), "l"(src));
}
#define CP_COMMIT asm volatile("cp.async.commit_group;" ::: "memory")
#define CP_WAIT1  asm volatile("cp.async.wait_group 1;" ::: "memory")
#define CP_WAIT0  asm volatile("cp.async.wait_group 0;" ::: "memory")

__device__ __forceinline__ uint32_t packhalf2(float c0, float c1)
{
    return ((uint32_t)__half_as_ushort(__float2half_rn(c1)) << 16)
         | __half_as_ushort(__float2half_rn(c0));
}
__device__ __forceinline__ float2 unpackhalf2(uint32_t v)
{
    __half2 h = *(__half2*)&v;
    return __half22float2(h);
}
__host__ __device__ constexpr int ilog2c(int v)
{
    int r = 0;
    while (v > 1) { v >>= 1; ++r; }
    return r;
}

// ===========================================================================
// Scratch buffers (activations in fp16 hi-pair format [b][ch/2][px])
// ===========================================================================
__device__ uint32_t g_w8_hp [(size_t)4*256*128*128];
__device__ uint32_t g_bwt_hp[(size_t)4*256*128*128];
__device__ uint32_t g_x_hp  [(size_t)4*32*256*256];
__device__ uint32_t g_r1_hp [(size_t)4*32*128*128];
__device__ uint32_t g_r2_hp [(size_t)4*256*128*128];
__device__ uint32_t g_wv_hp [(size_t)4*32*256*256];
__device__ float    g_pool  [(size_t)4*2*128*128];
__device__ float    g_sal   [(size_t)4*128*128];
__device__ float    g_m     [4*512];
__device__ float    g_cal   [4*512];
// weight images: exact smem layout, [coT][cc16][tap*512 + co*8 + swz(pos)]
__device__ uint32_t g_wi1[32*9*512];
__device__ uint32_t g_wi2[8*4*9*512];
__device__ uint32_t g_wi3[4*9*512];
__device__ uint32_t g_wif[4*512];
__device__ uint32_t g_wic[(size_t)4*8*32*512];

// ===========================================================================
// Weight prep: f32 [CO][CI][KS2] -> swizzled smem-image u32 (fp16 ci-pairs)
// ===========================================================================
__device__ __forceinline__ void packone(const float* __restrict__ w,
                                        uint32_t* __restrict__ wp,
                                        int CO, int CI, int KS2, int i)
{
    int chunkU = KS2*512;
    int perCoT = (CI/16)*chunkU;
    int coT = i / perCoT;
    int rem = i - coT*perCoT;
    int cc  = rem / chunkU;
    int u   = rem - cc*chunkU;
    int tap = u >> 9;
    int r   = u & 511;
    int co  = r >> 3, pos = r & 7;
    int xb  = (co>>2)&1;
    int cip = ((((pos>>2)^xb)<<2) | (pos&3));
    int ci  = cc*16 + 2*cip;
    int cog = coT*64 + co;
    wp[i] = packhalf2(w[((size_t)cog*CI + ci)*KS2 + tap],
                      w[((size_t)cog*CI + ci+1)*KS2 + tap]);
}
__global__ void packall_img(const float* __restrict__ w1, const float* __restrict__ w2,
                            const float* __restrict__ w3, const float* __restrict__ wf,
                            uint32_t* __restrict__ o1, uint32_t* __restrict__ o2,
                            uint32_t* __restrict__ o3, uint32_t* __restrict__ of)
{
    int i = blockIdx.x*256 + threadIdx.x;
    if (i < 147456)            packone(w1, o1, 64, 512, 9, i);
    else if (i < 294912)       packone(w2, o2, 512, 64, 9, i - 147456);
    else if (i < 313344)       packone(w3, o3, 64, 64, 9, i - 294912);
    else if (i < 315392)       packone(wf, of, 64, 64, 1, i - 313344);
}
__global__ void packwcal_img(const float* __restrict__ w, const float* __restrict__ cal,
                             uint32_t* __restrict__ wp)
{
    int i = blockIdx.x*256 + threadIdx.x;   // 4*131072
    int b = i >> 17;
    int rem = i & 131071;
    int coT = rem >> 14;
    int rem2 = rem & 16383;
    int cc  = rem2 >> 9;
    int u   = rem2 & 511;
    int co  = u >> 3, pos = u & 7;
    int xb  = (co>>2)&1;
    int cip = ((((pos>>2)^xb)<<2) | (pos&3));
    int ci  = cc*16 + 2*cip;
    int cog = coT*64 + co;
    wp[i] = packhalf2(w[cog*512 + ci]   * cal[b*512 + ci],
                      w[cog*512 + ci+1] * cal[b*512 + ci+1]);
}

// ===========================================================================
// K1: BWT  x -> bwt hi-pair, plus x repacked to hi-pair (for residual)
// ===========================================================================
__global__ void bwt_kernel(const float* __restrict__ x,
                           uint32_t* __restrict__ ohp, uint32_t* __restrict__ xhp)
{
    int idx = blockIdx.x * 256 + threadIdx.x;   // 4*32*128*128
    int j  = idx & 127;
    int i  = (idx >> 7) & 127;
    int cp = (idx >> 14) & 31;
    int b  = idx >> 19;
    const float* xp0 = x + ((size_t)(b*64 + 2*cp)*256 + 2*i)*256 + 2*j;
    const float* xp1 = xp0 + 65536;
    float2 r0 = *(const float2*)xp0, r1 = *(const float2*)(xp0 + 256);
    float2 s0 = *(const float2*)xp1, s1 = *(const float2*)(xp1 + 256);
    size_t xb = ((size_t)(b*32 + cp) << 16) + (size_t)(2*i)*256 + 2*j;
    xhp[xb      ] = packhalf2(r0.x, s0.x);
    xhp[xb + 1  ] = packhalf2(r0.y, s0.y);
    xhp[xb + 256] = packhalf2(r1.x, s1.x);
    xhp[xb + 257] = packhalf2(r1.y, s1.y);
    float a1 = r0.x*0.5f, a3 = r0.y*0.5f, a2 = r1.x*0.5f, a4 = r1.y*0.5f;
    float b1 = s0.x*0.5f, b3 = s0.y*0.5f, b2 = s1.x*0.5f, b4 = s1.y*0.5f;
    int p = (i << 7) + j;
    size_t obP = ((size_t)(b*256 + cp) << 14) + p;
    const size_t gsP = (size_t)32 << 14;
#define BWT_EMIT(k, s1_, s2_, s3_, s4_) \
    ohp[obP + k*gsP] = packhalf2(s1_ a1 s2_ a2 s3_ a3 s4_ a4, \
                                 s1_ b1 s2_ b2 s3_ b3 s4_ b4);
    BWT_EMIT(0, +, +, +, +)
    BWT_EMIT(1, -, -, +, +)
    BWT_EMIT(2, -, +, -, +)
    BWT_EMIT(3, +, -, -, +)
    BWT_EMIT(4, +, +, -, -)
    BWT_EMIT(5, -, +, +, -)
    BWT_EMIT(6, +, -, +, -)
    BWT_EMIT(7, -, -, -, -)
#undef BWT_EMIT
}

// ===========================================================================
// Implicit-GEMM conv, single-term fp16 mma.sync, m64 warp tile.
// A staged via 4B cp.async with PRECOMPUTED register descriptors
// (srcOffsetInChunk | dstSlot << SRCBITS; 0xFFFFFFFF = skip/OOB).
// OOB halo slots zero-filled ONCE at start. 3-stage A+W, 1 sync/chunk.
// ===========================================================================
template<int CIN, int COUT, int H, int KS, int KCH,
         bool RELU, bool ADD_OUT, bool ADD_HP, bool SAL, bool WPERB,
         bool OUTF32, bool OUTPK, int CIN2>
__global__ __launch_bounds__(256, 1)
void mmaconv_kernel(const uint32_t* __restrict__ in_hp,
                    const uint32_t* __restrict__ wimg,
                    const float* __restrict__ sal,
                    const uint32_t* __restrict__ addhp,
                    const uint32_t* __restrict__ in2_hp,
                    const uint32_t* __restrict__ wimg2,
                    float* outf, uint32_t* __restrict__ outhp)
{
    constexpr int KS2  = KS*KS;
    constexpr int PAD  = KS/2;
    constexpr int HCX  = 16 + KS - 1;
    constexpr int HCY  = 32 + KS - 1;
    constexpr int HEL  = HCX*HCY;
    constexpr int NSUB = KCH/16;
    constexpr int APL  = HEL*32;            // bytes per 16-ci sub-plane
    constexpr int ASTG = NSUB*APL;          // bytes per A stage
    constexpr int WCH  = NSUB*KS2*2048;     // bytes per W chunk
    constexpr int NC   = CIN/KCH;
    constexpr int ACNT = (KCH/2)*HEL;       // u32 per A stage
    constexpr int NA   = (ACNT + 255)/256;
    constexpr int NG   = NSUB*KS2*128;      // 16B granules per W chunk
    constexpr int HW   = H*H;
    constexpr int SRCBITS = ilog2c((KCH/2)*H*H);   // chunk-local src offset bits
    constexpr uint32_t SRCMASK = (1u << SRCBITS) - 1u;

    extern __shared__ __align__(16) char smem[];
    const uint32_t smemBase = (uint32_t)__cvta_generic_to_shared(smem);
    const uint32_t wSmem    = smemBase + 3*ASTG;

    const int t    = threadIdx.x;
    const int lane = t & 31, wid = t >> 5;
    const int g    = lane >> 2;
    const int c0   = (lane & 3) * 2;
    const int bx0  = blockIdx.x * 16;
    const int by0  = blockIdx.y * 32;
    const int z    = blockIdx.z;
    const int coT  = z % (COUT/64);
    const int b    = z / (COUT/64);

    const int ltile = lane >> 3, lrow = lane & 7;
    const int lt_lo = ltile & 1;
    const int lt_h  = ltile >> 1;

    uint32_t boff[4];
    #pragma unroll
    for (int nfp = 0; nfp < 4; ++nfp) {
        int cr = nfp*16 + lt_lo*8 + lrow;
        boff[nfp] = (uint32_t)(cr*32 + ((lt_h ^ ((cr>>2)&1)) << 4));
    }

    const size_t bciHW = (size_t)(b*(CIN/2))*HW;
    constexpr int NC16 = CIN/16;
    const uint32_t* wChunk0 = wimg
        + (WPERB ? (size_t)b*(COUT/64)*NC16*KS2*512 : 0)
        + (size_t)coT*NC16*KS2*512;

    float acc[4][8][4];
    #pragma unroll
    for (int mf = 0; mf < 4; ++mf)
        #pragma unroll
        for (int nf = 0; nf < 8; ++nf)
            #pragma unroll
            for (int q = 0; q < 4; ++q) acc[mf][nf][q] = 0.f;

    // ---- precompute A-staging descriptors (chunk-invariant) ----
    uint32_t desc[NA];
    #pragma unroll
    for (int k = 0; k < NA; ++k) {
        int idx = t + k*256;
        uint32_t d = 0xFFFFFFFFu;
        if (ACNT % 256 == 0 || idx < ACNT) {
            int cip = idx / HEL;
            int pix = idx - cip*HEL;
            int py  = pix / HCX, px = pix - py*HCX;
            int gy  = by0 + py - PAD, gx = bx0 + px - PAD;
            if (gy >= 0 && gy < H && gx >= 0 && gx < H) {
                int sub = cip >> 3, c8 = cip & 7;
                uint32_t u = sub*(HEL*8) + pix*8
                           + ((((c8>>2) ^ ((pix>>2)&1)) << 2) | (c8 & 3));
                d = (uint32_t)(cip*HW + gy*H + gx) | (u << SRCBITS);
            }
        }
        desc[k] = d;
    }
    // ---- zero-init all A stages (OOB slots stay zero forever) ----
    for (int k = t; k < 3*ASTG/4; k += 256)
        ((uint32_t*)smem)[k] = 0u;

    auto issueA = [&](const uint32_t* src, size_t chunkBase, int st) {
        const uint32_t dstB = smemBase + st*ASTG;
        #pragma unroll
        for (int k = 0; k < NA; ++k) {
            uint32_t d = desc[k];
            if (d != 0xFFFFFFFFu)
                cp4(dstB + (d >> SRCBITS)*4, src + chunkBase + (d & SRCMASK));
        }
    };
    auto cpW = [&](int cc, int st) {
        const uint32_t* src = wChunk0 + (size_t)cc*NSUB*KS2*512;
        uint32_t dst = wSmem + st*WCH;
        #pragma unroll
        for (int k = t; k < NG; k += 256)
            cp16(dst + k*16, src + k*4);
    };
    auto computeTap = [&](uint32_t aHi, uint32_t wTap, int dy, int dx) {
        uint32_t bh[8][2];
        #pragma unroll
        for (int nfp = 0; nfp < 4; ++nfp) {
            uint32_t tmp[4];
            ldsm_x4(tmp, wTap + boff[nfp]);
            bh[2*nfp][0] = tmp[0]; bh[2*nfp+1][0] = tmp[1];
            bh[2*nfp][1] = tmp[2]; bh[2*nfp+1][1] = tmp[3];
        }
        #pragma unroll
        for (int mf = 0; mf < 4; ++mf) {
            const int pyb = (wid << 2) + mf + dy;
            const int pix = pyb*HCX + dx + lt_lo*8 + lrow;
            uint32_t aoff = (uint32_t)(pix*32 + ((lt_h ^ ((pix>>2)&1)) << 4));
            uint32_t ah[4];
            ldsm_x4(ah, aHi + aoff);
            #pragma unroll
            for (int nf = 0; nf < 8; ++nf)
                mma_f16(acc[mf][nf], ah, bh[nf]);
        }
    };
    auto compute = [&](int st) {
        #pragma unroll
        for (int s = 0; s < NSUB; ++s) {
            const uint32_t aHi = smemBase + st*ASTG + s*APL;
            const uint32_t wB  = wSmem + st*WCH + s*KS2*2048;
            #pragma unroll
            for (int tap = 0; tap < KS2; ++tap)
                computeTap(aHi, wB + (uint32_t)(tap*2048), tap/KS, tap - (tap/KS)*KS);
        }
    };

    constexpr size_t CHSTRIDE = (size_t)(KCH/2)*HW;
    __syncthreads();   // zero-init visible before async writes land

    // ---- pipelined chunk loop: ONE sync per chunk, 3-stage A and W ----
    issueA(in_hp, bciHW, 0); cpW(0, 0); CP_COMMIT;
    if (NC > 1) { issueA(in_hp, bciHW + CHSTRIDE, 1); cpW(1, 1); }
    CP_COMMIT;
    CP_WAIT1;
    __syncthreads();
    #pragma unroll 1
    for (int cc = 0; cc < NC; ++cc) {
        compute(cc % 3);
        if (cc + 1 < NC) {
            if (cc + 2 < NC) {
                issueA(in_hp, bciHW + (size_t)(cc + 2)*CHSTRIDE, (cc + 2) % 3);
                cpW(cc + 2, (cc + 2) % 3);
            }
            CP_COMMIT;
            CP_WAIT1;
            __syncthreads();
        }
    }

    // ---- fused phase 2: relu + 1x1 conv of in2 accumulated on top ----
    if constexpr (CIN2 > 0) {
        #pragma unroll
        for (int mf = 0; mf < 4; ++mf)
            #pragma unroll
            for (int nf = 0; nf < 8; ++nf)
                #pragma unroll
                for (int q = 0; q < 4; ++q)
                    acc[mf][nf][q] = fmaxf(acc[mf][nf][q], 0.f);
        const size_t bci2 = (size_t)(b*(CIN2/2))*HW;
        #pragma unroll 1
        for (int cc = 0; cc < CIN2/16; ++cc) {
            __syncthreads();                       // release stage 0
            issueA(in2_hp, bci2 + (size_t)cc*CHSTRIDE, 0);
            for (int k = t; k < 512; k += 256)
                ((uint32_t*)(smem + 3*ASTG))[k] = wimg2[cc*512 + k];
            CP_COMMIT;
            CP_WAIT0;
            __syncthreads();
            computeTap(smemBase, wSmem, PAD, PAD);
        }
    }

    // ---- epilogue ----
    #pragma unroll
    for (int mf = 0; mf < 4; ++mf) {
        const int gy  = by0 + (wid << 2) + mf;
        const int gx0 = bx0 + g;
        const int gx8 = gx0 + 8;
        float s0 = 1.f, s8 = 1.f;
        if (SAL) {
            s0 = sal[((size_t)b*H + gy)*H + gx0];
            s8 = sal[((size_t)b*H + gy)*H + gx8];
        }
        #pragma unroll
        for (int nf = 0; nf < 8; ++nf) {
            const int co = coT*64 + nf*8 + c0;
            size_t o0 = ((size_t)(b*COUT + co)*H + gy)*H + gx0;
            size_t o1 = o0 + (size_t)H*H;
            size_t o2 = ((size_t)(b*COUT + co)*H + gy)*H + gx8;
            size_t o3 = o2 + (size_t)H*H;
            float v0 = acc[mf][nf][0]*s0, v1 = acc[mf][nf][1]*s0;
            float v2 = acc[mf][nf][2]*s8, v3 = acc[mf][nf][3]*s8;
            if (RELU && CIN2 == 0) {
                v0 = fmaxf(v0, 0.f); v1 = fmaxf(v1, 0.f);
                v2 = fmaxf(v2, 0.f); v3 = fmaxf(v3, 0.f);
            }
            if (ADD_OUT) { v0 += outf[o0]; v1 += outf[o1]; v2 += outf[o2]; v3 += outf[o3]; }
            size_t pb = ((size_t)(b*(COUT/2) + (co >> 1)))*HW + (size_t)gy*H;
            if (ADD_HP) {
                float2 h0 = unpackhalf2(addhp[pb + gx0]);
                float2 h8 = unpackhalf2(addhp[pb + gx8]);
                v0 += h0.x; v1 += h0.y; v2 += h8.x; v3 += h8.y;
            }
            if (OUTF32) { outf[o0] = v0; outf[o1] = v1; outf[o2] = v2; outf[o3] = v3; }
            if (OUTPK) {
                outhp[pb + gx0] = packhalf2(v0, v1);
                outhp[pb + gx8] = packhalf2(v2, v3);
            }
        }
    }
}

// ===========================================================================
// Attention glue kernels (hp inputs)
// ===========================================================================
__global__ void chanpool_kernel(const uint32_t* __restrict__ r2hp, float* __restrict__ pool)
{
    int p = blockIdx.x * 256 + threadIdx.x;
    int b = blockIdx.y;
    const uint32_t* base = r2hp + (((size_t)b*256) << 14) + p;
    float mx = -3.4e38f, s = 0.f;
    #pragma unroll 8
    for (int c = 0; c < 256; ++c) {
        float2 f = unpackhalf2(base[(size_t)c << 14]);
        mx = fmaxf(mx, fmaxf(f.x, f.y));
        s += f.x + f.y;
    }
    pool[(((size_t)(b*2    )) << 14) + p] = mx;
    pool[(((size_t)(b*2 + 1)) << 14) + p] = s * (1.f/512.f);
}

__global__ void salconv_kernel(const float* __restrict__ pool,
                               const float* __restrict__ wsal,
                               float* __restrict__ sal)
{
    int p = blockIdx.x * 256 + threadIdx.x;
    int b = blockIdx.y;
    int y = p >> 7, x = p & 127;
    float a = 0.f;
    #pragma unroll
    for (int c = 0; c < 2; ++c) {
        const float* pp = pool + (((size_t)(b*2 + c)) << 14);
        #pragma unroll
        for (int ky = 0; ky < 5; ++ky) {
            int iy = y + ky - 2;
            if (iy < 0 || iy >= 128) continue;
            #pragma unroll
            for (int kx = 0; kx < 5; ++kx) {
                int ix = x + kx - 2;
                if (ix < 0 || ix >= 128) continue;
                a += wsal[c*25 + ky*5 + kx] * pp[(iy << 7) + ix];
            }
        }
    }
    sal[(((size_t)b) << 14) + p] = 1.f / (1.f + expf(-a));
}

__global__ void wmean_kernel(const uint32_t* __restrict__ r2hp,
                             const float* __restrict__ sal,
                             float* __restrict__ m)
{
    int cp = blockIdx.x, b = blockIdx.y;
    const uint32_t* r = r2hp + (((size_t)(b*256 + cp)) << 14);
    const float* s = sal + (((size_t)b) << 14);
    float s0 = 0.f, s1 = 0.f;
    for (int i = threadIdx.x; i < 4096; i += 256) {
        uint4 rv = *(const uint4*)(r + i*4);
        float4 sv = *(const float4*)(s + i*4);
        float2 f0 = unpackhalf2(rv.x), f1 = unpackhalf2(rv.y);
        float2 f2 = unpackhalf2(rv.z), f3 = unpackhalf2(rv.w);
        s0 += f0.x*sv.x + f1.x*sv.y + f2.x*sv.z + f3.x*sv.w;
        s1 += f0.y*sv.x + f1.y*sv.y + f2.y*sv.z + f3.y*sv.w;
    }
    #pragma unroll
    for (int o = 16; o > 0; o >>= 1) {
        s0 += __shfl_xor_sync(0xffffffffu, s0, o);
        s1 += __shfl_xor_sync(0xffffffffu, s1, o);
    }
    __shared__ float red[8][2];
    if ((threadIdx.x & 31) == 0) {
        red[threadIdx.x >> 5][0] = s0;
        red[threadIdx.x >> 5][1] = s1;
    }
    __syncthreads();
    if (threadIdx.x == 0) {
        float t0 = 0.f, t1 = 0.f;
        #pragma unroll
        for (int i = 0; i < 8; ++i) { t0 += red[i][0]; t1 += red[i][1]; }
        m[b*512 + 2*cp    ] = t0 * (1.f/16384.f);
        m[b*512 + 2*cp + 1] = t1 * (1.f/16384.f);
    }
}

__global__ void calmlp_kernel(const float* __restrict__ m,
                              const float* __restrict__ wca1,
                              const float* __restrict__ wca2,
                              float* __restrict__ cal)
{
    int b = blockIdx.x;
    __shared__ float sm[512];
    __shared__ float sy1[32];
    for (int i = threadIdx.x; i < 512; i += 256) sm[i] = m[b*512 + i];
    __syncthreads();
    if (threadIdx.x < 32) {
        float a = 0.f;
        for (int c = 0; c < 512; ++c) a += wca1[threadIdx.x*512 + c] * sm[c];
        sy1[threadIdx.x] = fmaxf(a, 0.f);
    }
    __syncthreads();
    for (int c = threadIdx.x; c < 512; c += 256) {
        float a = 0.f;
        #pragma unroll
        for (int j = 0; j < 32; ++j) a += wca2[c*32 + j] * sy1[j];
        cal[b*512 + c] = 1.f / (1.f + expf(-a));
    }
}

// ===========================================================================
// K9: IBWT (hp in from conv8) -> hi-pair packed output
// ===========================================================================
__global__ void ibwt_kernel(const uint32_t* __restrict__ rhp, uint32_t* __restrict__ ohp)
{
    int idx = blockIdx.x * 256 + threadIdx.x;
    int j  = idx & 127;
    int i  = (idx >> 7) & 127;
    int cp = (idx >> 14) & 31;
    int b  = idx >> 19;
    int p  = (i << 7) + j;
    size_t base = ((size_t)(b*256 + cp) << 14) + p;
    const size_t gsP = (size_t)32 << 14;
    float pe[8], qe[8];
    #pragma unroll
    for (int s = 0; s < 8; ++s) {
        float2 f = unpackhalf2(rhp[base + s*gsP]);
        pe[s] = f.x*0.5f; qe[s] = f.y*0.5f;
    }
    float a00p = pe[0]-pe[1]-pe[2]+pe[3]+pe[4]-pe[5]+pe[6]-pe[7];
    float a10p = pe[0]-pe[1]+pe[2]-pe[3]-pe[4]+pe[5]-pe[6]+pe[7];
    float a01p = pe[0]+pe[1]-pe[2]-pe[3]-pe[4]-pe[5]+pe[6]+pe[7];
    float a11p = pe[0]+pe[1]+pe[2]+pe[3]+pe[4]+pe[5]+pe[6]+pe[7];
    float a00q = qe[0]-qe[1]-qe[2]+qe[3]+qe[4]-qe[5]+qe[6]-qe[7];
    float a10q = qe[0]-qe[1]+qe[2]-qe[3]-qe[4]+qe[5]-qe[6]+qe[7];
    float a01q = qe[0]+qe[1]-qe[2]-qe[3]-qe[4]-qe[5]+qe[6]+qe[7];
    float a11q = qe[0]+qe[1]+qe[2]+qe[3]+qe[4]+qe[5]+qe[6]+qe[7];
    size_t off = ((size_t)(b*32 + cp) << 16) + ((size_t)(2*i))*256 + 2*j;
    ohp[off      ] = packhalf2(a00p, a00q);
    ohp[off + 1  ] = packhalf2(a01p, a01q);
    ohp[off + 256] = packhalf2(a10p, a10q);
    ohp[off + 257] = packhalf2(a11p, a11q);
}

// ===========================================================================
// Launch
// ===========================================================================
extern "C" void kernel_launch(void* const* d_in, const int* in_sizes, int n_in,
                              void* d_out, int out_size)
{
    const float* x       = (const float*)d_in[0];
    const float* w_body1 = (const float*)d_in[1];
    const float* w_body2 = (const float*)d_in[2];
    const float* w_sal   = (const float*)d_in[3];
    const float* w_ca1   = (const float*)d_in[4];
    const float* w_ca2   = (const float*)d_in[5];
    const float* w_1x1   = (const float*)d_in[6];
    const float* w_3x3   = (const float*)d_in[7];
    const float* w_final = (const float*)d_in[8];
    float* out = (float*)d_out;

    float *pool, *sal, *m, *cal;
    uint32_t *w8_hp, *bwt_hp, *x_hp, *r1_hp, *r2_hp, *wv_hp;
    uint32_t *wi1, *wi2, *wi3, *wif, *wic;
    cudaGetSymbolAddress((void**)&w8_hp,  g_w8_hp);
    cudaGetSymbolAddress((void**)&bwt_hp, g_bwt_hp);
    cudaGetSymbolAddress((void**)&x_hp,   g_x_hp);
    cudaGetSymbolAddress((void**)&r1_hp,  g_r1_hp);
    cudaGetSymbolAddress((void**)&r2_hp,  g_r2_hp);
    cudaGetSymbolAddress((void**)&wv_hp,  g_wv_hp);
    cudaGetSymbolAddress((void**)&pool,   g_pool);
    cudaGetSymbolAddress((void**)&sal,    g_sal);
    cudaGetSymbolAddress((void**)&m,      g_m);
    cudaGetSymbolAddress((void**)&cal,    g_cal);
    cudaGetSymbolAddress((void**)&wi1,    g_wi1);
    cudaGetSymbolAddress((void**)&wi2,    g_wi2);
    cudaGetSymbolAddress((void**)&wi3,    g_wi3);
    cudaGetSymbolAddress((void**)&wif,    g_wif);
    cudaGetSymbolAddress((void**)&wic,    g_wic);

    // smem: KS=3 MF=4 -> 3*(34*18*32) + 3*(9*2048) = 114048
    //       KS=1 KCH=32 -> 3*(2*32*16*32) + 3*(2*2048) = 110592
    constexpr int SM3    = 3*(34*18*32) + 3*(9*2048);
    constexpr int SM1K32 = 3*(2*32*16*32) + 3*(2*2048);
    cudaFuncSetAttribute(
        (const void*)mmaconv_kernel<512,64,128,3,16, true,false,false,false,false,false,true,0>,
        cudaFuncAttributeMaxDynamicSharedMemorySize, SM3);
    cudaFuncSetAttribute(
        (const void*)mmaconv_kernel<64,512,128,3,16, false,false,false,false,false,false,true,0>,
        cudaFuncAttributeMaxDynamicSharedMemorySize, SM3);
    cudaFuncSetAttribute(
        (const void*)mmaconv_kernel<512,512,128,1,32, false,false,true,true,true,false,true,0>,
        cudaFuncAttributeMaxDynamicSharedMemorySize, SM1K32);
    cudaFuncSetAttribute(
        (const void*)mmaconv_kernel<64,64,256,3,16, true,false,false,false,false,true,false,64>,
        cudaFuncAttributeMaxDynamicSharedMemorySize, SM3);

    // 0) all static weight images in one launch
    packall_img<<<(315392 + 255)/256, 256>>>(w_body1, w_body2, w_3x3, w_final,
                                             wi1, wi2, wi3, wif);

    // 1) BWT (hi-pair) + x repack
    bwt_kernel<<<8192, 256>>>(x, bwt_hp, x_hp);
    // 2) body1 3x3 (512 -> 64) + relu -> r1 hi-pair
    mmaconv_kernel<512,64,128,3,16, true,false,false,false,false,false,true,0>
        <<<dim3(8,4,4), 256, SM3>>>(bwt_hp, wi1, nullptr, nullptr, nullptr, nullptr,
                                    nullptr, r1_hp);
    // 3) body2 3x3 (64 -> 512) -> r2 hi-pair
    mmaconv_kernel<64,512,128,3,16, false,false,false,false,false,false,true,0>
        <<<dim3(8,4,32), 256, SM3>>>(r1_hp, wi2, nullptr, nullptr, nullptr, nullptr,
                                     nullptr, r2_hp);
    // 4) channel pooling (hp)
    chanpool_kernel<<<dim3(64,4), 256>>>(r2_hp, pool);
    // 5) 5x5 conv + sigmoid -> sal
    salconv_kernel<<<dim3(64,4), 256>>>(pool, w_sal, sal);
    // 6) weighted channel means (hp, pairs)
    wmean_kernel<<<dim3(256,4), 256>>>(r2_hp, sal, m);
    // 7) channel attention MLP
    calmlp_kernel<<<4, 256>>>(m, w_ca1, w_ca2, cal);
    // 7b) 1x1 weights with cal folded (per batch), swizzled image
    packwcal_img<<<(4*8*32*512)/256, 256>>>(w_1x1, cal, wic);
    // 8) 1x1 conv (512->512), KCH=32: sal epilogue, += x_bwt hp -> w8 hp
    mmaconv_kernel<512,512,128,1,32, false,false,true,true,true,false,true,0>
        <<<dim3(8,4,32), 256, SM1K32>>>(r2_hp, wic, sal, bwt_hp, nullptr, nullptr,
                                        nullptr, w8_hp);
    // 9) IBWT (hp in) -> hi-pair wave
    ibwt_kernel<<<8192, 256>>>(w8_hp, wv_hp);
    // 10+11 fused) out = relu(conv3x3(wave)) + conv1x1(x)
    mmaconv_kernel<64,64,256,3,16, true,false,false,false,false,true,false,64>
        <<<dim3(16,8,4), 256, SM3>>>(wv_hp, wi3, nullptr, nullptr, x_hp, wif,
                                     out, nullptr);
}